// round 6
// baseline (speedup 1.0000x reference)
#include <cuda_runtime.h>
#include <cuda_bf16.h>
#include <math_constants.h>
#include <cstdint>

#define E_DIM 1024
#define BATCH 2
#define SEQ   2048
#define NHEAD 16
#define HDIM  64
#define MTOT  4096   // BATCH*SEQ

// ======================= scratch =======================
__device__ __nv_bfloat16 g_h_hi [MTOT * E_DIM];
__device__ __nv_bfloat16 g_h_lo [MTOT * E_DIM];
__device__ __nv_bfloat16 g_o_hi [MTOT * E_DIM];
__device__ __nv_bfloat16 g_o_lo [MTOT * E_DIM];
__device__ float         g_x2   [MTOT * E_DIM];
__device__ __nv_bfloat16 g_mb_hi[MTOT * 4 * E_DIM];   // reused: qkv hi, then mlp hidden hi
__device__ __nv_bfloat16 g_mb_lo[MTOT * 4 * E_DIM];   // reused: qkv lo, then mlp hidden lo
__device__ __nv_bfloat16 g_wi_hi[3 * E_DIM * E_DIM];
__device__ __nv_bfloat16 g_wi_lo[3 * E_DIM * E_DIM];
__device__ __nv_bfloat16 g_wo_hi[E_DIM * E_DIM];
__device__ __nv_bfloat16 g_wo_lo[E_DIM * E_DIM];
__device__ __nv_bfloat16 g_wf_hi[4 * E_DIM * E_DIM];
__device__ __nv_bfloat16 g_wf_lo[4 * E_DIM * E_DIM];
__device__ __nv_bfloat16 g_wp_hi[E_DIM * 4 * E_DIM];
__device__ __nv_bfloat16 g_wp_lo[E_DIM * 4 * E_DIM];

__device__ __forceinline__ void split_bf16(float x, __nv_bfloat16& h, __nv_bfloat16& l) {
    h = __float2bfloat16_rn(x);
    l = __float2bfloat16_rn(x - __bfloat162float(h));
}
__device__ __forceinline__ void split_pack(float f0, float f1, uint32_t& h, uint32_t& l) {
    __nv_bfloat16 h0, l0, h1, l1;
    split_bf16(f0, h0, l0); split_bf16(f1, h1, l1);
    __nv_bfloat162 hh = {h0, h1}, ll = {l0, l1};
    h = *(uint32_t*)&hh; l = *(uint32_t*)&ll;
}

__device__ __forceinline__ uint32_t smem_u32(const void* p) {
    uint32_t a;
    asm("{ .reg .u64 t; cvta.to.shared.u64 t, %1; cvt.u32.u64 %0, t; }" : "=r"(a) : "l"(p));
    return a;
}
__device__ __forceinline__ void ldsm_x4(uint32_t (&r)[4], uint32_t addr) {
    asm volatile("ldmatrix.sync.aligned.m8n8.x4.shared.b16 {%0,%1,%2,%3}, [%4];"
                 : "=r"(r[0]), "=r"(r[1]), "=r"(r[2]), "=r"(r[3]) : "r"(addr));
}
__device__ __forceinline__ void ldsm_x2_trans(uint32_t (&r)[2], uint32_t addr) {
    asm volatile("ldmatrix.sync.aligned.m8n8.x2.trans.shared.b16 {%0,%1}, [%2];"
                 : "=r"(r[0]), "=r"(r[1]) : "r"(addr));
}
__device__ __forceinline__ void mma16816(float (&d)[4], const uint32_t (&a)[4],
                                         uint32_t b0, uint32_t b1) {
    asm volatile("mma.sync.aligned.m16n8k16.row.col.f32.bf16.bf16.f32 "
                 "{%0,%1,%2,%3}, {%4,%5,%6,%7}, {%8,%9}, {%0,%1,%2,%3};"
                 : "+f"(d[0]), "+f"(d[1]), "+f"(d[2]), "+f"(d[3])
                 : "r"(a[0]), "r"(a[1]), "r"(a[2]), "r"(a[3]), "r"(b0), "r"(b1));
}
__device__ __forceinline__ void cp_async16(uint32_t saddr, const void* gaddr) {
    asm volatile("cp.async.cg.shared.global [%0], [%1], 16;" :: "r"(saddr), "l"(gaddr));
}
__device__ __forceinline__ void cp_commit() {
    asm volatile("cp.async.commit_group;" ::: "memory");
}
template<int N> __device__ __forceinline__ void cp_wait() {
    asm volatile("cp.async.wait_group %0;" :: "n"(N) : "memory");
}

// ======================= fused weight convert =======================
#define WI_N4 (3 * E_DIM * E_DIM / 4)
#define WO_N4 (E_DIM * E_DIM / 4)
#define WF_N4 (4 * E_DIM * E_DIM / 4)
#define WP_N4 (4 * E_DIM * E_DIM / 4)
#define CVT_TOT (WI_N4 + WO_N4 + WF_N4 + WP_N4)

__global__ __launch_bounds__(256) void cvt_all(
    const float* __restrict__ w_in, const float* __restrict__ w_out,
    const float* __restrict__ w_fc, const float* __restrict__ w_proj,
    __nv_bfloat16* __restrict__ wi_hi, __nv_bfloat16* __restrict__ wi_lo,
    __nv_bfloat16* __restrict__ wo_hi, __nv_bfloat16* __restrict__ wo_lo,
    __nv_bfloat16* __restrict__ wf_hi, __nv_bfloat16* __restrict__ wf_lo,
    __nv_bfloat16* __restrict__ wp_hi, __nv_bfloat16* __restrict__ wp_lo)
{
    const int stride = gridDim.x * blockDim.x;
    for (int i = blockIdx.x * blockDim.x + threadIdx.x; i < CVT_TOT; i += stride) {
        const float* src; __nv_bfloat16 *hi, *lo; int j = i;
        if (j < WI_N4)                { src = w_in;   hi = wi_hi; lo = wi_lo; }
        else if ((j -= WI_N4) < WO_N4){ src = w_out;  hi = wo_hi; lo = wo_lo; }
        else if ((j -= WO_N4) < WF_N4){ src = w_fc;   hi = wf_hi; lo = wf_lo; }
        else { j -= WF_N4;              src = w_proj; hi = wp_hi; lo = wp_lo; }
        float4 v = ((const float4*)src)[j];
        __nv_bfloat16 h0, h1, h2, h3, l0, l1, l2, l3;
        split_bf16(v.x, h0, l0); split_bf16(v.y, h1, l1);
        split_bf16(v.z, h2, l2); split_bf16(v.w, h3, l3);
        __nv_bfloat162* ph = (__nv_bfloat162*)&hi[(size_t)j * 4];
        __nv_bfloat162* pl = (__nv_bfloat162*)&lo[(size_t)j * 4];
        ph[0] = {h0, h1}; ph[1] = {h2, h3};
        pl[0] = {l0, l1}; pl[1] = {l2, l3};
    }
}

// ======================= layernorm (emits hi/lo bf16) =======================
__global__ __launch_bounds__(256) void ln_kernel(const float* __restrict__ x,
                                                 __nv_bfloat16* __restrict__ yhi,
                                                 __nv_bfloat16* __restrict__ ylo) {
    __shared__ float rs[8], rq[8];
    const int row = blockIdx.x;
    const int tid = threadIdx.x;
    float4 v = ((const float4*)(x + (size_t)row * E_DIM))[tid];
    float s  = v.x + v.y + v.z + v.w;
    float sq = v.x*v.x + v.y*v.y + v.z*v.z + v.w*v.w;
#pragma unroll
    for (int o = 16; o; o >>= 1) {
        s  += __shfl_xor_sync(0xffffffffu, s,  o);
        sq += __shfl_xor_sync(0xffffffffu, sq, o);
    }
    if ((tid & 31) == 0) { rs[tid >> 5] = s; rq[tid >> 5] = sq; }
    __syncthreads();
    if (tid < 32) {
        s  = (tid < 8) ? rs[tid] : 0.f;
        sq = (tid < 8) ? rq[tid] : 0.f;
#pragma unroll
        for (int o = 4; o; o >>= 1) {
            s  += __shfl_xor_sync(0xffffffffu, s,  o);
            sq += __shfl_xor_sync(0xffffffffu, sq, o);
        }
        if (tid == 0) { rs[0] = s; rq[0] = sq; }
    }
    __syncthreads();
    const float mean = rs[0] * (1.0f / E_DIM);
    const float var  = rq[0] * (1.0f / E_DIM) - mean * mean;
    const float rstd = rsqrtf(var + 1e-5f);
    float y0 = (v.x - mean) * rstd, y1 = (v.y - mean) * rstd;
    float y2 = (v.z - mean) * rstd, y3 = (v.w - mean) * rstd;
    __nv_bfloat16 h0, h1, h2, h3, l0, l1, l2, l3;
    split_bf16(y0, h0, l0); split_bf16(y1, h1, l1);
    split_bf16(y2, h2, l2); split_bf16(y3, h3, l3);
    __nv_bfloat162* ph = (__nv_bfloat162*)&yhi[(size_t)row * E_DIM + tid * 4];
    __nv_bfloat162* pl = (__nv_bfloat162*)&ylo[(size_t)row * E_DIM + tid * 4];
    ph[0] = {h0, h1}; ph[1] = {h2, h3};
    pl[0] = {l0, l1}; pl[1] = {l2, l3};
}

// ======================= 128x128 GEMM (wo / proj) =======================
// MODE 2: +res fp32 | 3: +bias+res fp32
#define TILE_BYTES  16384
#define STAGE_BYTES (4 * TILE_BYTES)
#define GEMM_STAGES 3
#define GEMM_SMEM   (GEMM_STAGES * STAGE_BYTES)   // 192 KB

template<int MODE>
__global__ __launch_bounds__(256) void gemm_tc(
    const __nv_bfloat16* __restrict__ Ah, const __nv_bfloat16* __restrict__ Al,
    const __nv_bfloat16* __restrict__ Bh, const __nv_bfloat16* __restrict__ Bl,
    const float* __restrict__ bias, const float* __restrict__ res,
    float* __restrict__ Cf, __nv_bfloat16* __restrict__ Chi,
    __nv_bfloat16* __restrict__ Clo, int M, int N, int K)
{
    extern __shared__ char smem[];
    const uint32_t sbase = smem_u32(smem);
    const int tid  = threadIdx.x;
    const int wid  = tid >> 5;
    const int lane = tid & 31;
    const int row0 = blockIdx.y * 128;
    const int col0 = blockIdx.x * 128;
    const int wm = (wid & 1) * 64;
    const int wn = (wid >> 1) * 32;

    float acc[4][4][4];
#pragma unroll
    for (int i = 0; i < 4; i++)
#pragma unroll
        for (int j = 0; j < 4; j++)
#pragma unroll
            for (int k = 0; k < 4; k++) acc[i][j][k] = 0.f;

    const int NC = K >> 6;

    auto issue_stage = [&](int c) {
        const uint32_t st = sbase + (c % GEMM_STAGES) * STAGE_BYTES;
        const int k0 = c << 6;
#pragma unroll
        for (int t = 0; t < 4; t++) {
            const __nv_bfloat16* g = (t == 0) ? Ah : (t == 1) ? Al : (t == 2) ? Bh : Bl;
            const int rbase = (t < 2) ? row0 : col0;
            const uint32_t tb = st + t * TILE_BYTES;
#pragma unroll
            for (int i = 0; i < 4; i++) {
                const int idx = tid + i * 256;
                const int r = idx >> 3, cc = idx & 7;
                cp_async16(tb + r * 128 + ((cc ^ (r & 7)) << 4),
                           g + (size_t)(rbase + r) * K + k0 + cc * 8);
            }
        }
        cp_commit();
    };

    issue_stage(0);
    if (NC > 1) issue_stage(1);

    for (int c = 0; c < NC; c++) {
        if (c < NC - 1) cp_wait<1>();
        else            cp_wait<0>();
        __syncthreads();
        if (c + 2 < NC) issue_stage(c + 2);

        const uint32_t st  = sbase + (c % GEMM_STAGES) * STAGE_BYTES;
        const uint32_t sAh = st;
        const uint32_t sAl = st + TILE_BYTES;
        const uint32_t sBh = st + 2 * TILE_BYTES;
        const uint32_t sBl = st + 3 * TILE_BYTES;
        const int g  = lane >> 3;
        const int lr = lane & 7;

#pragma unroll
        for (int ks = 0; ks < 4; ks++) {
            const int kc0 = ks * 2;
            uint32_t ah[4][4], al[4][4], bh[4][2], bl[4][2];
#pragma unroll
            for (int mt = 0; mt < 4; mt++) {
                const int row = wm + mt * 16 + lr + (g & 1) * 8;
                const int ch  = kc0 + (g >> 1);
                const uint32_t off = row * 128 + ((ch ^ (row & 7)) << 4);
                ldsm_x4(ah[mt], sAh + off);
                ldsm_x4(al[mt], sAl + off);
            }
#pragma unroll
            for (int np = 0; np < 2; np++) {
                const int row = wn + np * 16 + lr + (g >> 1) * 8;
                const int ch  = kc0 + (g & 1);
                const uint32_t off = row * 128 + ((ch ^ (row & 7)) << 4);
                uint32_t t0[4], t1[4];
                ldsm_x4(t0, sBh + off);
                ldsm_x4(t1, sBl + off);
                bh[np*2][0] = t0[0]; bh[np*2][1] = t0[1];
                bh[np*2+1][0] = t0[2]; bh[np*2+1][1] = t0[3];
                bl[np*2][0] = t1[0]; bl[np*2][1] = t1[1];
                bl[np*2+1][0] = t1[2]; bl[np*2+1][1] = t1[3];
            }
#pragma unroll
            for (int mt = 0; mt < 4; mt++)
#pragma unroll
                for (int nt = 0; nt < 4; nt++) {
                    mma16816(acc[mt][nt], ah[mt], bh[nt][0], bh[nt][1]);
                    mma16816(acc[mt][nt], ah[mt], bl[nt][0], bl[nt][1]);
                    mma16816(acc[mt][nt], al[mt], bh[nt][0], bh[nt][1]);
                }
        }
    }

#pragma unroll
    for (int mt = 0; mt < 4; mt++) {
#pragma unroll
        for (int nt = 0; nt < 4; nt++) {
            const int r0 = row0 + wm + mt * 16 + (lane >> 2);
            const int r1 = r0 + 8;
            const int cc = col0 + wn + nt * 8 + (lane & 3) * 2;
            float v0 = acc[mt][nt][0], v1 = acc[mt][nt][1];
            float v2 = acc[mt][nt][2], v3 = acc[mt][nt][3];
            if (MODE == 3) {
                const float b0 = bias[cc], b1 = bias[cc + 1];
                v0 += b0; v1 += b1; v2 += b0; v3 += b1;
            }
            float2 ra = *(const float2*)&res[(size_t)r0 * N + cc];
            float2 rb = *(const float2*)&res[(size_t)r1 * N + cc];
            v0 += ra.x; v1 += ra.y; v2 += rb.x; v3 += rb.y;
            *(float2*)&Cf[(size_t)r0 * N + cc] = {v0, v1};
            *(float2*)&Cf[(size_t)r1 * N + cc] = {v2, v3};
        }
    }
}

// ======================= 256x128 GEMM, 512 threads (qkv / fc) =======================
// MODE 1: relu(+bias)->bf16 hi/lo | 4: ->bf16 hi/lo
#define BT_A 32768                       // 256 rows x 128 B
#define BT_B 16384                       // 128 rows x 128 B
#define BIG_STAGE (2 * BT_A + 2 * BT_B)  // 96 KB
#define BIG_SMEM  (2 * BIG_STAGE)        // 192 KB

template<int MODE>
__global__ __launch_bounds__(512) void gemm_big(
    const __nv_bfloat16* __restrict__ Ah, const __nv_bfloat16* __restrict__ Al,
    const __nv_bfloat16* __restrict__ Bh, const __nv_bfloat16* __restrict__ Bl,
    const float* __restrict__ bias,
    __nv_bfloat16* __restrict__ Chi, __nv_bfloat16* __restrict__ Clo,
    int M, int N, int K)
{
    extern __shared__ char smem[];
    const uint32_t sbase = smem_u32(smem);
    const int tid  = threadIdx.x;
    const int wid  = tid >> 5;     // 0..15
    const int lane = tid & 31;
    const int row0 = blockIdx.y * 256;
    const int col0 = blockIdx.x * 128;
    const int wm = (wid & 3) * 64;
    const int wn = (wid >> 2) * 32;

    float acc[4][4][4];
#pragma unroll
    for (int i = 0; i < 4; i++)
#pragma unroll
        for (int j = 0; j < 4; j++)
#pragma unroll
            for (int k = 0; k < 4; k++) acc[i][j][k] = 0.f;

    const int NC = K >> 6;

    auto issue_stage = [&](int c) {
        const uint32_t st = sbase + (c & 1) * BIG_STAGE;
        const int k0 = c << 6;
        // A tiles: 256 rows
#pragma unroll
        for (int t = 0; t < 2; t++) {
            const __nv_bfloat16* g = t ? Al : Ah;
            const uint32_t tb = st + t * BT_A;
#pragma unroll
            for (int i = 0; i < 4; i++) {
                const int idx = tid + i * 512;
                const int r = idx >> 3, cc = idx & 7;
                cp_async16(tb + r * 128 + ((cc ^ (r & 7)) << 4),
                           g + (size_t)(row0 + r) * K + k0 + cc * 8);
            }
        }
        // B tiles: 128 rows
#pragma unroll
        for (int t = 0; t < 2; t++) {
            const __nv_bfloat16* g = t ? Bl : Bh;
            const uint32_t tb = st + 2 * BT_A + t * BT_B;
#pragma unroll
            for (int i = 0; i < 2; i++) {
                const int idx = tid + i * 512;
                const int r = idx >> 3, cc = idx & 7;
                cp_async16(tb + r * 128 + ((cc ^ (r & 7)) << 4),
                           g + (size_t)(col0 + r) * K + k0 + cc * 8);
            }
        }
        cp_commit();
    };

    issue_stage(0);
    if (NC > 1) issue_stage(1);

    for (int c = 0; c < NC; c++) {
        if (c < NC - 1) cp_wait<1>();
        else            cp_wait<0>();
        __syncthreads();

        const uint32_t st  = sbase + (c & 1) * BIG_STAGE;
        const uint32_t sAh = st;
        const uint32_t sAl = st + BT_A;
        const uint32_t sBh = st + 2 * BT_A;
        const uint32_t sBl = st + 2 * BT_A + BT_B;
        const int g  = lane >> 3;
        const int lr = lane & 7;

#pragma unroll
        for (int ks = 0; ks < 4; ks++) {
            const int kc0 = ks * 2;
            uint32_t ah[4][4], al[4][4], bh[4][2], bl[4][2];
#pragma unroll
            for (int mt = 0; mt < 4; mt++) {
                const int row = wm + mt * 16 + lr + (g & 1) * 8;
                const int ch  = kc0 + (g >> 1);
                const uint32_t off = row * 128 + ((ch ^ (row & 7)) << 4);
                ldsm_x4(ah[mt], sAh + off);
                ldsm_x4(al[mt], sAl + off);
            }
#pragma unroll
            for (int np = 0; np < 2; np++) {
                const int row = wn + np * 16 + lr + (g >> 1) * 8;
                const int ch  = kc0 + (g & 1);
                const uint32_t off = row * 128 + ((ch ^ (row & 7)) << 4);
                uint32_t t0[4], t1[4];
                ldsm_x4(t0, sBh + off);
                ldsm_x4(t1, sBl + off);
                bh[np*2][0] = t0[0]; bh[np*2][1] = t0[1];
                bh[np*2+1][0] = t0[2]; bh[np*2+1][1] = t0[3];
                bl[np*2][0] = t1[0]; bl[np*2][1] = t1[1];
                bl[np*2+1][0] = t1[2]; bl[np*2+1][1] = t1[3];
            }
#pragma unroll
            for (int mt = 0; mt < 4; mt++)
#pragma unroll
                for (int nt = 0; nt < 4; nt++) {
                    mma16816(acc[mt][nt], ah[mt], bh[nt][0], bh[nt][1]);
                    mma16816(acc[mt][nt], ah[mt], bl[nt][0], bl[nt][1]);
                    mma16816(acc[mt][nt], al[mt], bh[nt][0], bh[nt][1]);
                }
        }
        __syncthreads();
        if (c + 2 < NC) issue_stage(c + 2);
    }

#pragma unroll
    for (int mt = 0; mt < 4; mt++) {
#pragma unroll
        for (int nt = 0; nt < 4; nt++) {
            const int r0 = row0 + wm + mt * 16 + (lane >> 2);
            const int r1 = r0 + 8;
            const int cc = col0 + wn + nt * 8 + (lane & 3) * 2;
            float v0 = acc[mt][nt][0], v1 = acc[mt][nt][1];
            float v2 = acc[mt][nt][2], v3 = acc[mt][nt][3];
            if (MODE == 1) {
                const float b0 = bias[cc], b1 = bias[cc + 1];
                v0 = fmaxf(v0 + b0, 0.f); v1 = fmaxf(v1 + b1, 0.f);
                v2 = fmaxf(v2 + b0, 0.f); v3 = fmaxf(v3 + b1, 0.f);
            }
            __nv_bfloat16 h0, h1, h2, h3, l0, l1, l2, l3;
            split_bf16(v0, h0, l0); split_bf16(v1, h1, l1);
            split_bf16(v2, h2, l2); split_bf16(v3, h3, l3);
            *(__nv_bfloat162*)&Chi[(size_t)r0 * N + cc] = {h0, h1};
            *(__nv_bfloat162*)&Chi[(size_t)r1 * N + cc] = {h2, h3};
            *(__nv_bfloat162*)&Clo[(size_t)r0 * N + cc] = {l0, l1};
            *(__nv_bfloat162*)&Clo[(size_t)r1 * N + cc] = {l2, l3};
        }
    }
}

// ======================= MMA causal flash attention =======================
// CTA: 128 q rows (8 warps x 16), KV tiles of 64, double-buffered. 96 KB smem, 2 CTAs/SM.
#define ATT_SMEM 98304

__global__ __launch_bounds__(256, 2) void attn_mma(
    const __nv_bfloat16* __restrict__ qkvh, const __nv_bfloat16* __restrict__ qkvl,
    __nv_bfloat16* __restrict__ ohi, __nv_bfloat16* __restrict__ olo)
{
    extern __shared__ char smem[];
    const uint32_t sb = smem_u32(smem);
    const int tid = threadIdx.x, wid = tid >> 5, lane = tid & 31;
    const int qb = (int)gridDim.x - 1 - (int)blockIdx.x;   // longest blocks first
    const int q0 = qb * 128;
    const int h  = blockIdx.y, b = blockIdx.z;
    const int LD = 3 * E_DIM;
    const size_t base = (size_t)b * SEQ * LD + (size_t)h * HDIM;

    const uint32_t sQh = sb, sQl = sb + 16384;

#pragma unroll
    for (int i = 0; i < 4; i++) {
        const int idx = tid + i * 256;
        const int r = idx >> 3, cc = idx & 7;
        const uint32_t soff = r * 128 + ((cc ^ (r & 7)) << 4);
        cp_async16(sQh + soff, qkvh + base + (size_t)(q0 + r) * LD + cc * 8);
        cp_async16(sQl + soff, qkvl + base + (size_t)(q0 + r) * LD + cc * 8);
    }
    auto issue_kv = [&](int t) {
        const uint32_t st = sb + 32768 + (t & 1) * 32768;
        const int k0 = t * 64;
#pragma unroll
        for (int i = 0; i < 2; i++) {
            const int idx = tid + i * 256;
            const int r = idx >> 3, cc = idx & 7;
            const uint32_t soff = r * 128 + ((cc ^ (r & 7)) << 4);
            const size_t gk = base + E_DIM     + (size_t)(k0 + r) * LD + cc * 8;
            const size_t gv = base + 2 * E_DIM + (size_t)(k0 + r) * LD + cc * 8;
            cp_async16(st +         soff, qkvh + gk);
            cp_async16(st + 8192  + soff, qkvl + gk);
            cp_async16(st + 16384 + soff, qkvh + gv);
            cp_async16(st + 24576 + soff, qkvl + gv);
        }
        cp_commit();
    };
    issue_kv(0);

    const int ntiles = (q0 >> 6) + 2;
    const int g = lane >> 2, tig = lane & 3;
    const int lr = lane & 7, gg = lane >> 3;

    float oacc[8][4];
#pragma unroll
    for (int j = 0; j < 8; j++)
#pragma unroll
        for (int e = 0; e < 4; e++) oacc[j][e] = 0.f;
    float m0 = -CUDART_INF_F, m1 = -CUDART_INF_F, l0 = 0.f, l1 = 0.f;
    uint32_t qfh[4][4], qfl[4][4];
    const float scale = 0.125f;

    for (int t = 0; t < ntiles; t++) {
        if (t + 1 < ntiles) { issue_kv(t + 1); cp_wait<1>(); }
        else                { cp_wait<0>(); }
        __syncthreads();
        if (t == 0) {
            const int row = wid * 16 + lr + (gg & 1) * 8;
#pragma unroll
            for (int kc = 0; kc < 4; kc++) {
                const int ch = kc * 2 + (gg >> 1);
                const uint32_t off = row * 128 + ((ch ^ (row & 7)) << 4);
                ldsm_x4(qfh[kc], sQh + off);
                ldsm_x4(qfl[kc], sQl + off);
            }
        }
        const uint32_t sKh = sb + 32768 + (t & 1) * 32768;
        const uint32_t sKl = sKh + 8192;
        const uint32_t sVh = sKh + 16384;
        const uint32_t sVl = sKh + 24576;

        float S[8][4];
#pragma unroll
        for (int j = 0; j < 8; j++)
#pragma unroll
            for (int e = 0; e < 4; e++) S[j][e] = 0.f;
#pragma unroll
        for (int kc = 0; kc < 4; kc++) {
            uint32_t bh[8][2], bl[8][2];
#pragma unroll
            for (int jp = 0; jp < 4; jp++) {
                const int row = jp * 16 + lr + (gg >> 1) * 8;
                const int ch  = kc * 2 + (gg & 1);
                const uint32_t off = row * 128 + ((ch ^ (row & 7)) << 4);
                uint32_t t0[4], t1[4];
                ldsm_x4(t0, sKh + off);
                ldsm_x4(t1, sKl + off);
                bh[jp*2][0] = t0[0]; bh[jp*2][1] = t0[1];
                bh[jp*2+1][0] = t0[2]; bh[jp*2+1][1] = t0[3];
                bl[jp*2][0] = t1[0]; bl[jp*2][1] = t1[1];
                bl[jp*2+1][0] = t1[2]; bl[jp*2+1][1] = t1[3];
            }
#pragma unroll
            for (int j = 0; j < 8; j++) {
                mma16816(S[j], qfh[kc], bh[j][0], bh[j][1]);
                mma16816(S[j], qfh[kc], bl[j][0], bl[j][1]);
                mma16816(S[j], qfl[kc], bh[j][0], bh[j][1]);
            }
        }

        const int k0 = t * 64;
        const int r0 = q0 + wid * 16 + g, r1 = r0 + 8;
        const bool need_mask = (k0 + 63 > q0 + wid * 16);
#pragma unroll
        for (int j = 0; j < 8; j++) {
#pragma unroll
            for (int e = 0; e < 4; e++) S[j][e] *= scale;
            if (need_mask) {
                const int c0 = k0 + j * 8 + tig * 2, c1 = c0 + 1;
                if (c0 > r0) S[j][0] = -CUDART_INF_F;
                if (c1 > r0) S[j][1] = -CUDART_INF_F;
                if (c0 > r1) S[j][2] = -CUDART_INF_F;
                if (c1 > r1) S[j][3] = -CUDART_INF_F;
            }
        }

        float rx0 = -CUDART_INF_F, rx1 = -CUDART_INF_F;
#pragma unroll
        for (int j = 0; j < 8; j++) {
            rx0 = fmaxf(rx0, fmaxf(S[j][0], S[j][1]));
            rx1 = fmaxf(rx1, fmaxf(S[j][2], S[j][3]));
        }
        rx0 = fmaxf(rx0, __shfl_xor_sync(0xffffffffu, rx0, 1));
        rx0 = fmaxf(rx0, __shfl_xor_sync(0xffffffffu, rx0, 2));
        rx1 = fmaxf(rx1, __shfl_xor_sync(0xffffffffu, rx1, 1));
        rx1 = fmaxf(rx1, __shfl_xor_sync(0xffffffffu, rx1, 2));
        const float nm0 = fmaxf(m0, rx0), nm1 = fmaxf(m1, rx1);
        const float cr0 = __expf(m0 - nm0), cr1 = __expf(m1 - nm1);
        float sm0 = 0.f, sm1 = 0.f;
#pragma unroll
        for (int j = 0; j < 8; j++) {
            S[j][0] = __expf(S[j][0] - nm0); sm0 += S[j][0];
            S[j][1] = __expf(S[j][1] - nm0); sm0 += S[j][1];
            S[j][2] = __expf(S[j][2] - nm1); sm1 += S[j][2];
            S[j][3] = __expf(S[j][3] - nm1); sm1 += S[j][3];
        }
        sm0 += __shfl_xor_sync(0xffffffffu, sm0, 1);
        sm0 += __shfl_xor_sync(0xffffffffu, sm0, 2);
        sm1 += __shfl_xor_sync(0xffffffffu, sm1, 1);
        sm1 += __shfl_xor_sync(0xffffffffu, sm1, 2);
        l0 = l0 * cr0 + sm0; l1 = l1 * cr1 + sm1;
        m0 = nm0; m1 = nm1;
#pragma unroll
        for (int j = 0; j < 8; j++) {
            oacc[j][0] *= cr0; oacc[j][1] *= cr0;
            oacc[j][2] *= cr1; oacc[j][3] *= cr1;
        }

        const int kvr = (lane & 15);
#pragma unroll
        for (int kc = 0; kc < 4; kc++) {
            uint32_t ph[4], pl[4];
            split_pack(S[2*kc][0],   S[2*kc][1],   ph[0], pl[0]);
            split_pack(S[2*kc][2],   S[2*kc][3],   ph[1], pl[1]);
            split_pack(S[2*kc+1][0], S[2*kc+1][1], ph[2], pl[2]);
            split_pack(S[2*kc+1][2], S[2*kc+1][3], ph[3], pl[3]);
            const int vr = kc * 16 + kvr;
#pragma unroll
            for (int j = 0; j < 8; j++) {
                const uint32_t off = vr * 128 + ((j ^ (vr & 7)) << 4);
                uint32_t vh[2], vl[2];
                ldsm_x2_trans(vh, sVh + off);
                ldsm_x2_trans(vl, sVl + off);
                mma16816(oacc[j], ph, vh[0], vh[1]);
                mma16816(oacc[j], ph, vl[0], vl[1]);
                mma16816(oacc[j], pl, vh[0], vh[1]);
            }
        }
        __syncthreads();
    }

    const float i0 = 1.0f / l0, i1 = 1.0f / l1;
    const int row0 = q0 + wid * 16 + g;
    const size_t gr0 = ((size_t)b * SEQ + row0) * E_DIM;
    const size_t gr1 = gr0 + 8 * E_DIM;
#pragma unroll
    for (int j = 0; j < 8; j++) {
        const int c = h * HDIM + j * 8 + tig * 2;
        __nv_bfloat16 h0, h1, h2, h3, q0b, q1b, q2b, q3b;
        split_bf16(oacc[j][0] * i0, h0, q0b);
        split_bf16(oacc[j][1] * i0, h1, q1b);
        split_bf16(oacc[j][2] * i1, h2, q2b);
        split_bf16(oacc[j][3] * i1, h3, q3b);
        *(__nv_bfloat162*)&ohi[gr0 + c] = {h0, h1};
        *(__nv_bfloat162*)&olo[gr0 + c] = {q0b, q1b};
        *(__nv_bfloat162*)&ohi[gr1 + c] = {h2, h3};
        *(__nv_bfloat162*)&olo[gr1 + c] = {q2b, q3b};
    }
}

// ======================= launch =======================
extern "C" void kernel_launch(void* const* d_in, const int* in_sizes, int n_in,
                              void* d_out, int out_size) {
    const float* x      = (const float*)d_in[0];
    const float* w_in   = (const float*)d_in[1];
    const float* w_out  = (const float*)d_in[2];
    const float* w_fc   = (const float*)d_in[3];
    const float* b_fc   = (const float*)d_in[4];
    const float* w_proj = (const float*)d_in[5];
    const float* b_proj = (const float*)d_in[6];
    float* out = (float*)d_out;

    __nv_bfloat16 *h_hi, *h_lo, *o_hi, *o_lo, *mb_hi, *mb_lo;
    __nv_bfloat16 *wi_hi, *wi_lo, *wo_hi, *wo_lo, *wf_hi, *wf_lo, *wp_hi, *wp_lo;
    float *x2;
    cudaGetSymbolAddress((void**)&h_hi,  g_h_hi);  cudaGetSymbolAddress((void**)&h_lo,  g_h_lo);
    cudaGetSymbolAddress((void**)&o_hi,  g_o_hi);  cudaGetSymbolAddress((void**)&o_lo,  g_o_lo);
    cudaGetSymbolAddress((void**)&x2,    g_x2);
    cudaGetSymbolAddress((void**)&mb_hi, g_mb_hi); cudaGetSymbolAddress((void**)&mb_lo, g_mb_lo);
    cudaGetSymbolAddress((void**)&wi_hi, g_wi_hi); cudaGetSymbolAddress((void**)&wi_lo, g_wi_lo);
    cudaGetSymbolAddress((void**)&wo_hi, g_wo_hi); cudaGetSymbolAddress((void**)&wo_lo, g_wo_lo);
    cudaGetSymbolAddress((void**)&wf_hi, g_wf_hi); cudaGetSymbolAddress((void**)&wf_lo, g_wf_lo);
    cudaGetSymbolAddress((void**)&wp_hi, g_wp_hi); cudaGetSymbolAddress((void**)&wp_lo, g_wp_lo);

    cudaFuncSetAttribute(gemm_tc<2>, cudaFuncAttributeMaxDynamicSharedMemorySize, GEMM_SMEM);
    cudaFuncSetAttribute(gemm_tc<3>, cudaFuncAttributeMaxDynamicSharedMemorySize, GEMM_SMEM);
    cudaFuncSetAttribute(gemm_big<1>, cudaFuncAttributeMaxDynamicSharedMemorySize, BIG_SMEM);
    cudaFuncSetAttribute(gemm_big<4>, cudaFuncAttributeMaxDynamicSharedMemorySize, BIG_SMEM);
    cudaFuncSetAttribute(attn_mma,   cudaFuncAttributeMaxDynamicSharedMemorySize, ATT_SMEM);

    cvt_all<<<2048, 256>>>(w_in, w_out, w_fc, w_proj,
                           wi_hi, wi_lo, wo_hi, wo_lo, wf_hi, wf_lo, wp_hi, wp_lo);

    // h = ln(x) -> bf16 split
    ln_kernel<<<MTOT, 256>>>(x, h_hi, h_lo);
    // qkv = h @ w_in^T -> bf16 hi/lo (into mb buffers)
    gemm_big<4><<<dim3(3 * E_DIM / 128, MTOT / 256), 512, BIG_SMEM>>>(
        h_hi, h_lo, wi_hi, wi_lo, nullptr, mb_hi, mb_lo, MTOT, 3 * E_DIM, E_DIM);
    // o = causal_attn(qkv) -> bf16 hi/lo
    attn_mma<<<dim3(SEQ / 128, NHEAD, BATCH), 256, ATT_SMEM>>>(mb_hi, mb_lo, o_hi, o_lo);
    // x2 = x + o @ w_out^T
    gemm_tc<2><<<dim3(E_DIM / 128, MTOT / 128), 256, GEMM_SMEM>>>(
        o_hi, o_lo, wo_hi, wo_lo, nullptr, x, x2, nullptr, nullptr,
        MTOT, E_DIM, E_DIM);
    // h = ln(x2) -> bf16 split
    ln_kernel<<<MTOT, 256>>>(x2, h_hi, h_lo);
    // mb = relu(h @ w_fc^T + b_fc) -> bf16 hi/lo
    gemm_big<1><<<dim3(4 * E_DIM / 128, MTOT / 256), 512, BIG_SMEM>>>(
        h_hi, h_lo, wf_hi, wf_lo, b_fc, mb_hi, mb_lo, MTOT, 4 * E_DIM, E_DIM);
    // out = mb @ w_proj^T + b_proj + x2
    gemm_tc<3><<<dim3(E_DIM / 128, MTOT / 128), 256, GEMM_SMEM>>>(
        mb_hi, mb_lo, wp_hi, wp_lo, b_proj, x2, out, nullptr, nullptr,
        MTOT, E_DIM, 4 * E_DIM);
}

// round 7
// speedup vs baseline: 1.3742x; 1.3742x over previous
#include <cuda_runtime.h>
#include <cuda_fp16.h>
#include <math_constants.h>
#include <cstdint>

#define E_DIM 1024
#define BATCH 2
#define SEQ   2048
#define NHEAD 16
#define HDIM  64
#define MTOT  4096   // BATCH*SEQ

// ======================= scratch =======================
__device__ __half g_h_hi [MTOT * E_DIM];
__device__ __half g_h_lo [MTOT * E_DIM];
__device__ __half g_o_hi [MTOT * E_DIM];
__device__ __half g_o_lo [MTOT * E_DIM];
__device__ float  g_x2   [MTOT * E_DIM];
__device__ __half g_mb_hi[MTOT * 4 * E_DIM];   // reused: qkv hi, then mlp hidden hi
__device__ __half g_mb_lo[MTOT * 4 * E_DIM];   // reused: qkv lo, then mlp hidden lo
__device__ __half g_wi   [3 * E_DIM * E_DIM];  // weights: fp16 hi only
__device__ __half g_wo   [E_DIM * E_DIM];
__device__ __half g_wf   [4 * E_DIM * E_DIM];
__device__ __half g_wp   [E_DIM * 4 * E_DIM];

__device__ __forceinline__ void split_f16(float x, __half& h, __half& l) {
    h = __float2half_rn(x);
    l = __float2half_rn(x - __half2float(h));
}
__device__ __forceinline__ void split_pack16(float f0, float f1, uint32_t& h, uint32_t& l) {
    __half h0, l0, h1, l1;
    split_f16(f0, h0, l0); split_f16(f1, h1, l1);
    __half2 hh = __halves2half2(h0, h1), ll = __halves2half2(l0, l1);
    h = *(uint32_t*)&hh; l = *(uint32_t*)&ll;
}

__device__ __forceinline__ uint32_t smem_u32(const void* p) {
    uint32_t a;
    asm("{ .reg .u64 t; cvta.to.shared.u64 t, %1; cvt.u32.u64 %0, t; }" : "=r"(a) : "l"(p));
    return a;
}
__device__ __forceinline__ void ldsm_x4(uint32_t (&r)[4], uint32_t addr) {
    asm volatile("ldmatrix.sync.aligned.m8n8.x4.shared.b16 {%0,%1,%2,%3}, [%4];"
                 : "=r"(r[0]), "=r"(r[1]), "=r"(r[2]), "=r"(r[3]) : "r"(addr));
}
__device__ __forceinline__ void ldsm_x2_trans(uint32_t (&r)[2], uint32_t addr) {
    asm volatile("ldmatrix.sync.aligned.m8n8.x2.trans.shared.b16 {%0,%1}, [%2];"
                 : "=r"(r[0]), "=r"(r[1]) : "r"(addr));
}
__device__ __forceinline__ void mma16816(float (&d)[4], const uint32_t (&a)[4],
                                         uint32_t b0, uint32_t b1) {
    asm volatile("mma.sync.aligned.m16n8k16.row.col.f32.f16.f16.f32 "
                 "{%0,%1,%2,%3}, {%4,%5,%6,%7}, {%8,%9}, {%0,%1,%2,%3};"
                 : "+f"(d[0]), "+f"(d[1]), "+f"(d[2]), "+f"(d[3])
                 : "r"(a[0]), "r"(a[1]), "r"(a[2]), "r"(a[3]), "r"(b0), "r"(b1));
}
__device__ __forceinline__ void cp_async16(uint32_t saddr, const void* gaddr) {
    asm volatile("cp.async.cg.shared.global [%0], [%1], 16;" :: "r"(saddr), "l"(gaddr));
}
__device__ __forceinline__ void cp_commit() {
    asm volatile("cp.async.commit_group;" ::: "memory");
}
template<int N> __device__ __forceinline__ void cp_wait() {
    asm volatile("cp.async.wait_group %0;" :: "n"(N) : "memory");
}

// ======================= fused weight convert (hi only) =======================
#define WI_N4 (3 * E_DIM * E_DIM / 4)
#define WO_N4 (E_DIM * E_DIM / 4)
#define WF_N4 (4 * E_DIM * E_DIM / 4)
#define WP_N4 (4 * E_DIM * E_DIM / 4)
#define CVT_TOT (WI_N4 + WO_N4 + WF_N4 + WP_N4)

__global__ __launch_bounds__(256) void cvt_all(
    const float* __restrict__ w_in, const float* __restrict__ w_out,
    const float* __restrict__ w_fc, const float* __restrict__ w_proj,
    __half* __restrict__ wi, __half* __restrict__ wo,
    __half* __restrict__ wf, __half* __restrict__ wp)
{
    const int stride = gridDim.x * blockDim.x;
    for (int i = blockIdx.x * blockDim.x + threadIdx.x; i < CVT_TOT; i += stride) {
        const float* src; __half* dst; int j = i;
        if (j < WI_N4)                { src = w_in;   dst = wi; }
        else if ((j -= WI_N4) < WO_N4){ src = w_out;  dst = wo; }
        else if ((j -= WO_N4) < WF_N4){ src = w_fc;   dst = wf; }
        else { j -= WF_N4;              src = w_proj; dst = wp; }
        float4 v = ((const float4*)src)[j];
        __half2* p = (__half2*)&dst[(size_t)j * 4];
        p[0] = __halves2half2(__float2half_rn(v.x), __float2half_rn(v.y));
        p[1] = __halves2half2(__float2half_rn(v.z), __float2half_rn(v.w));
    }
}

// ======================= layernorm (emits hi/lo fp16) =======================
__global__ __launch_bounds__(256) void ln_kernel(const float* __restrict__ x,
                                                 __half* __restrict__ yhi,
                                                 __half* __restrict__ ylo) {
    __shared__ float rs[8], rq[8];
    const int row = blockIdx.x;
    const int tid = threadIdx.x;
    float4 v = ((const float4*)(x + (size_t)row * E_DIM))[tid];
    float s  = v.x + v.y + v.z + v.w;
    float sq = v.x*v.x + v.y*v.y + v.z*v.z + v.w*v.w;
#pragma unroll
    for (int o = 16; o; o >>= 1) {
        s  += __shfl_xor_sync(0xffffffffu, s,  o);
        sq += __shfl_xor_sync(0xffffffffu, sq, o);
    }
    if ((tid & 31) == 0) { rs[tid >> 5] = s; rq[tid >> 5] = sq; }
    __syncthreads();
    if (tid < 32) {
        s  = (tid < 8) ? rs[tid] : 0.f;
        sq = (tid < 8) ? rq[tid] : 0.f;
#pragma unroll
        for (int o = 4; o; o >>= 1) {
            s  += __shfl_xor_sync(0xffffffffu, s,  o);
            sq += __shfl_xor_sync(0xffffffffu, sq, o);
        }
        if (tid == 0) { rs[0] = s; rq[0] = sq; }
    }
    __syncthreads();
    const float mean = rs[0] * (1.0f / E_DIM);
    const float var  = rq[0] * (1.0f / E_DIM) - mean * mean;
    const float rstd = rsqrtf(var + 1e-5f);
    float y0 = (v.x - mean) * rstd, y1 = (v.y - mean) * rstd;
    float y2 = (v.z - mean) * rstd, y3 = (v.w - mean) * rstd;
    __half h0, h1, h2, h3, l0, l1, l2, l3;
    split_f16(y0, h0, l0); split_f16(y1, h1, l1);
    split_f16(y2, h2, l2); split_f16(y3, h3, l3);
    __half2* ph = (__half2*)&yhi[(size_t)row * E_DIM + tid * 4];
    __half2* pl = (__half2*)&ylo[(size_t)row * E_DIM + tid * 4];
    ph[0] = __halves2half2(h0, h1); ph[1] = __halves2half2(h2, h3);
    pl[0] = __halves2half2(l0, l1); pl[1] = __halves2half2(l2, l3);
}

// ======================= fp16 2-pass tensor GEMM =======================
// C[M,N] = (Ah+Al)[M,K] * Bh[N,K]^T
// MODE 1: relu(+bias)->f16 hi/lo | 2: +res fp32 | 3: +bias+res fp32 | 4: ->f16 hi/lo
#define TILE_BYTES  16384               // 128 rows x 128 bytes (64 fp16)
#define STAGE_BYTES (3 * TILE_BYTES)    // Ah, Al, Bh
#define GEMM_STAGES 3
#define GEMM_SMEM   (GEMM_STAGES * STAGE_BYTES)   // 144 KB

template<int MODE>
__global__ __launch_bounds__(256) void gemm_tc(
    const __half* __restrict__ Ah, const __half* __restrict__ Al,
    const __half* __restrict__ Bh,
    const float* __restrict__ bias, const float* __restrict__ res,
    float* __restrict__ Cf, __half* __restrict__ Chi,
    __half* __restrict__ Clo, int M, int N, int K)
{
    extern __shared__ char smem[];
    const uint32_t sbase = smem_u32(smem);
    const int tid  = threadIdx.x;
    const int wid  = tid >> 5;
    const int lane = tid & 31;
    const int row0 = blockIdx.y * 128;
    const int col0 = blockIdx.x * 128;
    const int wm = (wid & 1) * 64;
    const int wn = (wid >> 1) * 32;

    float acc[4][4][4];
#pragma unroll
    for (int i = 0; i < 4; i++)
#pragma unroll
        for (int j = 0; j < 4; j++)
#pragma unroll
            for (int k = 0; k < 4; k++) acc[i][j][k] = 0.f;

    const int NC = K >> 6;

    auto issue_stage = [&](int c) {
        const uint32_t st = sbase + (c % GEMM_STAGES) * STAGE_BYTES;
        const int k0 = c << 6;
#pragma unroll
        for (int t = 0; t < 3; t++) {
            const __half* g = (t == 0) ? Ah : (t == 1) ? Al : Bh;
            const int rbase = (t < 2) ? row0 : col0;
            const uint32_t tb = st + t * TILE_BYTES;
#pragma unroll
            for (int i = 0; i < 4; i++) {
                const int idx = tid + i * 256;
                const int r = idx >> 3, cc = idx & 7;
                cp_async16(tb + r * 128 + ((cc ^ (r & 7)) << 4),
                           g + (size_t)(rbase + r) * K + k0 + cc * 8);
            }
        }
        cp_commit();
    };

    issue_stage(0);
    if (NC > 1) issue_stage(1);

    for (int c = 0; c < NC; c++) {
        if (c < NC - 1) cp_wait<1>();
        else            cp_wait<0>();
        __syncthreads();
        if (c + 2 < NC) issue_stage(c + 2);

        const uint32_t st  = sbase + (c % GEMM_STAGES) * STAGE_BYTES;
        const uint32_t sAh = st;
        const uint32_t sAl = st + TILE_BYTES;
        const uint32_t sBh = st + 2 * TILE_BYTES;
        const int g  = lane >> 3;
        const int lr = lane & 7;

#pragma unroll
        for (int ks = 0; ks < 4; ks++) {
            const int kc0 = ks * 2;
            uint32_t ah[4][4], al[4][4], bh[4][2];
#pragma unroll
            for (int mt = 0; mt < 4; mt++) {
                const int row = wm + mt * 16 + lr + (g & 1) * 8;
                const int ch  = kc0 + (g >> 1);
                const uint32_t off = row * 128 + ((ch ^ (row & 7)) << 4);
                ldsm_x4(ah[mt], sAh + off);
                ldsm_x4(al[mt], sAl + off);
            }
#pragma unroll
            for (int np = 0; np < 2; np++) {
                const int row = wn + np * 16 + lr + (g >> 1) * 8;
                const int ch  = kc0 + (g & 1);
                const uint32_t off = row * 128 + ((ch ^ (row & 7)) << 4);
                uint32_t t0[4];
                ldsm_x4(t0, sBh + off);
                bh[np*2][0] = t0[0]; bh[np*2][1] = t0[1];
                bh[np*2+1][0] = t0[2]; bh[np*2+1][1] = t0[3];
            }
#pragma unroll
            for (int mt = 0; mt < 4; mt++)
#pragma unroll
                for (int nt = 0; nt < 4; nt++) {
                    mma16816(acc[mt][nt], ah[mt], bh[nt][0], bh[nt][1]);
                    mma16816(acc[mt][nt], al[mt], bh[nt][0], bh[nt][1]);
                }
        }
    }

#pragma unroll
    for (int mt = 0; mt < 4; mt++) {
#pragma unroll
        for (int nt = 0; nt < 4; nt++) {
            const int r0 = row0 + wm + mt * 16 + (lane >> 2);
            const int r1 = r0 + 8;
            const int cc = col0 + wn + nt * 8 + (lane & 3) * 2;
            float v0 = acc[mt][nt][0], v1 = acc[mt][nt][1];
            float v2 = acc[mt][nt][2], v3 = acc[mt][nt][3];
            if (MODE == 1 || MODE == 3) {
                const float b0 = bias[cc], b1 = bias[cc + 1];
                v0 += b0; v1 += b1; v2 += b0; v3 += b1;
            }
            if (MODE == 1) {
                v0 = fmaxf(v0, 0.f); v1 = fmaxf(v1, 0.f);
                v2 = fmaxf(v2, 0.f); v3 = fmaxf(v3, 0.f);
            }
            if (MODE == 2 || MODE == 3) {
                float2 ra = *(const float2*)&res[(size_t)r0 * N + cc];
                float2 rb = *(const float2*)&res[(size_t)r1 * N + cc];
                v0 += ra.x; v1 += ra.y; v2 += rb.x; v3 += rb.y;
            }
            if (MODE == 1 || MODE == 4) {
                __half h0, h1, h2, h3, l0, l1, l2, l3;
                split_f16(v0, h0, l0); split_f16(v1, h1, l1);
                split_f16(v2, h2, l2); split_f16(v3, h3, l3);
                *(__half2*)&Chi[(size_t)r0 * N + cc] = __halves2half2(h0, h1);
                *(__half2*)&Chi[(size_t)r1 * N + cc] = __halves2half2(h2, h3);
                *(__half2*)&Clo[(size_t)r0 * N + cc] = __halves2half2(l0, l1);
                *(__half2*)&Clo[(size_t)r1 * N + cc] = __halves2half2(l2, l3);
            } else {
                *(float2*)&Cf[(size_t)r0 * N + cc] = {v0, v1};
                *(float2*)&Cf[(size_t)r1 * N + cc] = {v2, v3};
            }
        }
    }
}

// ======================= fp16 2-pass MMA causal flash attention =======================
// CTA: 128 q rows (8 warps x 16). KV tiles of 64 rows (K hi, V hi only), double-buffered.
// smem: Qh 16K | Ql 16K | stage{Kh 8K, Vh 8K} x2 = 64 KB -> 2 CTAs/SM.
#define ATT_SMEM 65536

__global__ __launch_bounds__(256, 2) void attn_mma(
    const __half* __restrict__ qkvh, const __half* __restrict__ qkvl,
    __half* __restrict__ ohi, __half* __restrict__ olo)
{
    extern __shared__ char smem[];
    const uint32_t sb = smem_u32(smem);
    const int tid = threadIdx.x, wid = tid >> 5, lane = tid & 31;
    const int qb = (int)gridDim.x - 1 - (int)blockIdx.x;   // longest blocks first
    const int q0 = qb * 128;
    const int h  = blockIdx.y, b = blockIdx.z;
    const int LD = 3 * E_DIM;
    const size_t base = (size_t)b * SEQ * LD + (size_t)h * HDIM;

    const uint32_t sQh = sb, sQl = sb + 16384;

#pragma unroll
    for (int i = 0; i < 4; i++) {
        const int idx = tid + i * 256;
        const int r = idx >> 3, cc = idx & 7;
        const uint32_t soff = r * 128 + ((cc ^ (r & 7)) << 4);
        cp_async16(sQh + soff, qkvh + base + (size_t)(q0 + r) * LD + cc * 8);
        cp_async16(sQl + soff, qkvl + base + (size_t)(q0 + r) * LD + cc * 8);
    }
    auto issue_kv = [&](int t) {
        const uint32_t st = sb + 32768 + (t & 1) * 16384;
        const int k0 = t * 64;
#pragma unroll
        for (int i = 0; i < 2; i++) {
            const int idx = tid + i * 256;
            const int r = idx >> 3, cc = idx & 7;
            const uint32_t soff = r * 128 + ((cc ^ (r & 7)) << 4);
            cp_async16(st +        soff, qkvh + base + E_DIM     + (size_t)(k0 + r) * LD + cc * 8);
            cp_async16(st + 8192 + soff, qkvh + base + 2 * E_DIM + (size_t)(k0 + r) * LD + cc * 8);
        }
        cp_commit();
    };
    issue_kv(0);

    const int ntiles = (q0 >> 6) + 2;
    const int g = lane >> 2, tig = lane & 3;
    const int lr = lane & 7, gg = lane >> 3;

    float oacc[8][4];
#pragma unroll
    for (int j = 0; j < 8; j++)
#pragma unroll
        for (int e = 0; e < 4; e++) oacc[j][e] = 0.f;
    float m0 = -CUDART_INF_F, m1 = -CUDART_INF_F, l0 = 0.f, l1 = 0.f;
    uint32_t qfh[4][4], qfl[4][4];
    const float scale = 0.125f;

    for (int t = 0; t < ntiles; t++) {
        if (t + 1 < ntiles) { issue_kv(t + 1); cp_wait<1>(); }
        else                { cp_wait<0>(); }
        __syncthreads();
        if (t == 0) {
            const int row = wid * 16 + lr + (gg & 1) * 8;
#pragma unroll
            for (int kc = 0; kc < 4; kc++) {
                const int ch = kc * 2 + (gg >> 1);
                const uint32_t off = row * 128 + ((ch ^ (row & 7)) << 4);
                ldsm_x4(qfh[kc], sQh + off);
                ldsm_x4(qfl[kc], sQl + off);
            }
        }
        const uint32_t sKh = sb + 32768 + (t & 1) * 16384;
        const uint32_t sVh = sKh + 8192;

        // ---- S = Q K^T (2-pass) ----
        float S[8][4];
#pragma unroll
        for (int j = 0; j < 8; j++)
#pragma unroll
            for (int e = 0; e < 4; e++) S[j][e] = 0.f;
#pragma unroll
        for (int kc = 0; kc < 4; kc++) {
            uint32_t bh[8][2];
#pragma unroll
            for (int jp = 0; jp < 4; jp++) {
                const int row = jp * 16 + lr + (gg >> 1) * 8;
                const int ch  = kc * 2 + (gg & 1);
                const uint32_t off = row * 128 + ((ch ^ (row & 7)) << 4);
                uint32_t t0[4];
                ldsm_x4(t0, sKh + off);
                bh[jp*2][0] = t0[0]; bh[jp*2][1] = t0[1];
                bh[jp*2+1][0] = t0[2]; bh[jp*2+1][1] = t0[3];
            }
#pragma unroll
            for (int j = 0; j < 8; j++) {
                mma16816(S[j], qfh[kc], bh[j][0], bh[j][1]);
                mma16816(S[j], qfl[kc], bh[j][0], bh[j][1]);
            }
        }

        // ---- scale + causal mask ----
        const int k0 = t * 64;
        const int r0 = q0 + wid * 16 + g, r1 = r0 + 8;
        const bool need_mask = (k0 + 63 > q0 + wid * 16);
#pragma unroll
        for (int j = 0; j < 8; j++) {
#pragma unroll
            for (int e = 0; e < 4; e++) S[j][e] *= scale;
            if (need_mask) {
                const int c0 = k0 + j * 8 + tig * 2, c1 = c0 + 1;
                if (c0 > r0) S[j][0] = -CUDART_INF_F;
                if (c1 > r0) S[j][1] = -CUDART_INF_F;
                if (c0 > r1) S[j][2] = -CUDART_INF_F;
                if (c1 > r1) S[j][3] = -CUDART_INF_F;
            }
        }

        // ---- online softmax ----
        float rx0 = -CUDART_INF_F, rx1 = -CUDART_INF_F;
#pragma unroll
        for (int j = 0; j < 8; j++) {
            rx0 = fmaxf(rx0, fmaxf(S[j][0], S[j][1]));
            rx1 = fmaxf(rx1, fmaxf(S[j][2], S[j][3]));
        }
        rx0 = fmaxf(rx0, __shfl_xor_sync(0xffffffffu, rx0, 1));
        rx0 = fmaxf(rx0, __shfl_xor_sync(0xffffffffu, rx0, 2));
        rx1 = fmaxf(rx1, __shfl_xor_sync(0xffffffffu, rx1, 1));
        rx1 = fmaxf(rx1, __shfl_xor_sync(0xffffffffu, rx1, 2));
        const float nm0 = fmaxf(m0, rx0), nm1 = fmaxf(m1, rx1);
        const float cr0 = __expf(m0 - nm0), cr1 = __expf(m1 - nm1);
        float sm0 = 0.f, sm1 = 0.f;
#pragma unroll
        for (int j = 0; j < 8; j++) {
            S[j][0] = __expf(S[j][0] - nm0); sm0 += S[j][0];
            S[j][1] = __expf(S[j][1] - nm0); sm0 += S[j][1];
            S[j][2] = __expf(S[j][2] - nm1); sm1 += S[j][2];
            S[j][3] = __expf(S[j][3] - nm1); sm1 += S[j][3];
        }
        sm0 += __shfl_xor_sync(0xffffffffu, sm0, 1);
        sm0 += __shfl_xor_sync(0xffffffffu, sm0, 2);
        sm1 += __shfl_xor_sync(0xffffffffu, sm1, 1);
        sm1 += __shfl_xor_sync(0xffffffffu, sm1, 2);
        l0 = l0 * cr0 + sm0; l1 = l1 * cr1 + sm1;
        m0 = nm0; m1 = nm1;
#pragma unroll
        for (int j = 0; j < 8; j++) {
            oacc[j][0] *= cr0; oacc[j][1] *= cr0;
            oacc[j][2] *= cr1; oacc[j][3] *= cr1;
        }

        // ---- O += P V (2-pass: P hi/lo, V hi) ----
        const int kvr = (lane & 15);
#pragma unroll
        for (int kc = 0; kc < 4; kc++) {
            uint32_t ph[4], pl[4];
            split_pack16(S[2*kc][0],   S[2*kc][1],   ph[0], pl[0]);
            split_pack16(S[2*kc][2],   S[2*kc][3],   ph[1], pl[1]);
            split_pack16(S[2*kc+1][0], S[2*kc+1][1], ph[2], pl[2]);
            split_pack16(S[2*kc+1][2], S[2*kc+1][3], ph[3], pl[3]);
            const int vr = kc * 16 + kvr;
#pragma unroll
            for (int j = 0; j < 8; j++) {
                const uint32_t off = vr * 128 + ((j ^ (vr & 7)) << 4);
                uint32_t vh[2];
                ldsm_x2_trans(vh, sVh + off);
                mma16816(oacc[j], ph, vh[0], vh[1]);
                mma16816(oacc[j], pl, vh[0], vh[1]);
            }
        }
        __syncthreads();
    }

    // ---- write O (fp16 hi/lo) ----
    const float i0 = 1.0f / l0, i1 = 1.0f / l1;
    const int row0 = q0 + wid * 16 + g;
    const size_t gr0 = ((size_t)b * SEQ + row0) * E_DIM;
    const size_t gr1 = gr0 + 8 * E_DIM;
#pragma unroll
    for (int j = 0; j < 8; j++) {
        const int c = h * HDIM + j * 8 + tig * 2;
        __half h0, h1, h2, h3, q0h, q1h, q2h, q3h;
        split_f16(oacc[j][0] * i0, h0, q0h);
        split_f16(oacc[j][1] * i0, h1, q1h);
        split_f16(oacc[j][2] * i1, h2, q2h);
        split_f16(oacc[j][3] * i1, h3, q3h);
        *(__half2*)&ohi[gr0 + c] = __halves2half2(h0, h1);
        *(__half2*)&olo[gr0 + c] = __halves2half2(q0h, q1h);
        *(__half2*)&ohi[gr1 + c] = __halves2half2(h2, h3);
        *(__half2*)&olo[gr1 + c] = __halves2half2(q2h, q3h);
    }
}

// ======================= launch =======================
extern "C" void kernel_launch(void* const* d_in, const int* in_sizes, int n_in,
                              void* d_out, int out_size) {
    const float* x      = (const float*)d_in[0];
    const float* w_in   = (const float*)d_in[1];
    const float* w_out  = (const float*)d_in[2];
    const float* w_fc   = (const float*)d_in[3];
    const float* b_fc   = (const float*)d_in[4];
    const float* w_proj = (const float*)d_in[5];
    const float* b_proj = (const float*)d_in[6];
    float* out = (float*)d_out;

    __half *h_hi, *h_lo, *o_hi, *o_lo, *mb_hi, *mb_lo, *wi, *wo, *wf, *wp;
    float *x2;
    cudaGetSymbolAddress((void**)&h_hi,  g_h_hi);  cudaGetSymbolAddress((void**)&h_lo,  g_h_lo);
    cudaGetSymbolAddress((void**)&o_hi,  g_o_hi);  cudaGetSymbolAddress((void**)&o_lo,  g_o_lo);
    cudaGetSymbolAddress((void**)&x2,    g_x2);
    cudaGetSymbolAddress((void**)&mb_hi, g_mb_hi); cudaGetSymbolAddress((void**)&mb_lo, g_mb_lo);
    cudaGetSymbolAddress((void**)&wi, g_wi); cudaGetSymbolAddress((void**)&wo, g_wo);
    cudaGetSymbolAddress((void**)&wf, g_wf); cudaGetSymbolAddress((void**)&wp, g_wp);

    cudaFuncSetAttribute(gemm_tc<1>, cudaFuncAttributeMaxDynamicSharedMemorySize, GEMM_SMEM);
    cudaFuncSetAttribute(gemm_tc<2>, cudaFuncAttributeMaxDynamicSharedMemorySize, GEMM_SMEM);
    cudaFuncSetAttribute(gemm_tc<3>, cudaFuncAttributeMaxDynamicSharedMemorySize, GEMM_SMEM);
    cudaFuncSetAttribute(gemm_tc<4>, cudaFuncAttributeMaxDynamicSharedMemorySize, GEMM_SMEM);
    cudaFuncSetAttribute(attn_mma,   cudaFuncAttributeMaxDynamicSharedMemorySize, ATT_SMEM);

    cvt_all<<<2048, 256>>>(w_in, w_out, w_fc, w_proj, wi, wo, wf, wp);

    // h = ln(x) -> fp16 split
    ln_kernel<<<MTOT, 256>>>(x, h_hi, h_lo);
    // qkv = h @ w_in^T -> fp16 hi/lo (into mb buffers)
    gemm_tc<4><<<dim3(3 * E_DIM / 128, MTOT / 128), 256, GEMM_SMEM>>>(
        h_hi, h_lo, wi, nullptr, nullptr, nullptr, mb_hi, mb_lo,
        MTOT, 3 * E_DIM, E_DIM);
    // o = causal_attn(qkv) -> fp16 hi/lo
    attn_mma<<<dim3(SEQ / 128, NHEAD, BATCH), 256, ATT_SMEM>>>(mb_hi, mb_lo, o_hi, o_lo);
    // x2 = x + o @ w_out^T
    gemm_tc<2><<<dim3(E_DIM / 128, MTOT / 128), 256, GEMM_SMEM>>>(
        o_hi, o_lo, wo, nullptr, x, x2, nullptr, nullptr,
        MTOT, E_DIM, E_DIM);
    // h = ln(x2) -> fp16 split
    ln_kernel<<<MTOT, 256>>>(x2, h_hi, h_lo);
    // mb = relu(h @ w_fc^T + b_fc) -> fp16 hi/lo
    gemm_tc<1><<<dim3(4 * E_DIM / 128, MTOT / 128), 256, GEMM_SMEM>>>(
        h_hi, h_lo, wf, b_fc, nullptr, nullptr, mb_hi, mb_lo,
        MTOT, 4 * E_DIM, E_DIM);
    // out = mb @ w_proj^T + b_proj + x2
    gemm_tc<3><<<dim3(E_DIM / 128, MTOT / 128), 256, GEMM_SMEM>>>(
        mb_hi, mb_lo, wp, b_proj, x2, out, nullptr, nullptr,
        MTOT, E_DIM, 4 * E_DIM);
}

// round 8
// speedup vs baseline: 2.4891x; 1.8114x over previous
#include <cuda_runtime.h>
#include <cuda_fp16.h>
#include <math_constants.h>
#include <cstdint>

#define E_DIM 1024
#define BATCH 2
#define SEQ   2048
#define NHEAD 16
#define HDIM  64
#define MTOT  4096   // BATCH*SEQ

// ======================= scratch =======================
__device__ __half g_h  [MTOT * E_DIM];
__device__ __half g_o  [MTOT * E_DIM];
__device__ float  g_x2 [MTOT * E_DIM];
__device__ __half g_mb [MTOT * 4 * E_DIM];   // reused: qkv, then mlp hidden
__device__ __half g_wi [3 * E_DIM * E_DIM];
__device__ __half g_wo [E_DIM * E_DIM];
__device__ __half g_wf [4 * E_DIM * E_DIM];
__device__ __half g_wp [E_DIM * 4 * E_DIM];

__device__ __forceinline__ uint32_t smem_u32(const void* p) {
    uint32_t a;
    asm("{ .reg .u64 t; cvta.to.shared.u64 t, %1; cvt.u32.u64 %0, t; }" : "=r"(a) : "l"(p));
    return a;
}
__device__ __forceinline__ void ldsm_x4(uint32_t (&r)[4], uint32_t addr) {
    asm volatile("ldmatrix.sync.aligned.m8n8.x4.shared.b16 {%0,%1,%2,%3}, [%4];"
                 : "=r"(r[0]), "=r"(r[1]), "=r"(r[2]), "=r"(r[3]) : "r"(addr));
}
__device__ __forceinline__ void ldsm_x2_trans(uint32_t (&r)[2], uint32_t addr) {
    asm volatile("ldmatrix.sync.aligned.m8n8.x2.trans.shared.b16 {%0,%1}, [%2];"
                 : "=r"(r[0]), "=r"(r[1]) : "r"(addr));
}
__device__ __forceinline__ void mma16816(float (&d)[4], const uint32_t (&a)[4],
                                         uint32_t b0, uint32_t b1) {
    asm volatile("mma.sync.aligned.m16n8k16.row.col.f32.f16.f16.f32 "
                 "{%0,%1,%2,%3}, {%4,%5,%6,%7}, {%8,%9}, {%0,%1,%2,%3};"
                 : "+f"(d[0]), "+f"(d[1]), "+f"(d[2]), "+f"(d[3])
                 : "r"(a[0]), "r"(a[1]), "r"(a[2]), "r"(a[3]), "r"(b0), "r"(b1));
}
__device__ __forceinline__ void cp_async16(uint32_t saddr, const void* gaddr) {
    asm volatile("cp.async.cg.shared.global [%0], [%1], 16;" :: "r"(saddr), "l"(gaddr));
}
__device__ __forceinline__ void cp_commit() {
    asm volatile("cp.async.commit_group;" ::: "memory");
}
template<int N> __device__ __forceinline__ void cp_wait() {
    asm volatile("cp.async.wait_group %0;" :: "n"(N) : "memory");
}

// ======================= fused weight convert =======================
#define WI_N4 (3 * E_DIM * E_DIM / 4)
#define WO_N4 (E_DIM * E_DIM / 4)
#define WF_N4 (4 * E_DIM * E_DIM / 4)
#define WP_N4 (4 * E_DIM * E_DIM / 4)
#define CVT_TOT (WI_N4 + WO_N4 + WF_N4 + WP_N4)

__global__ __launch_bounds__(256) void cvt_all(
    const float* __restrict__ w_in, const float* __restrict__ w_out,
    const float* __restrict__ w_fc, const float* __restrict__ w_proj,
    __half* __restrict__ wi, __half* __restrict__ wo,
    __half* __restrict__ wf, __half* __restrict__ wp)
{
    const int stride = gridDim.x * blockDim.x;
    for (int i = blockIdx.x * blockDim.x + threadIdx.x; i < CVT_TOT; i += stride) {
        const float* src; __half* dst; int j = i;
        if (j < WI_N4)                { src = w_in;   dst = wi; }
        else if ((j -= WI_N4) < WO_N4){ src = w_out;  dst = wo; }
        else if ((j -= WO_N4) < WF_N4){ src = w_fc;   dst = wf; }
        else { j -= WF_N4;              src = w_proj; dst = wp; }
        float4 v = ((const float4*)src)[j];
        __half2* p = (__half2*)&dst[(size_t)j * 4];
        p[0] = __halves2half2(__float2half_rn(v.x), __float2half_rn(v.y));
        p[1] = __halves2half2(__float2half_rn(v.z), __float2half_rn(v.w));
    }
}

// ======================= layernorm (emits fp16) =======================
__global__ __launch_bounds__(256) void ln_kernel(const float* __restrict__ x,
                                                 __half* __restrict__ y) {
    __shared__ float rs[8], rq[8];
    const int row = blockIdx.x;
    const int tid = threadIdx.x;
    float4 v = ((const float4*)(x + (size_t)row * E_DIM))[tid];
    float s  = v.x + v.y + v.z + v.w;
    float sq = v.x*v.x + v.y*v.y + v.z*v.z + v.w*v.w;
#pragma unroll
    for (int o = 16; o; o >>= 1) {
        s  += __shfl_xor_sync(0xffffffffu, s,  o);
        sq += __shfl_xor_sync(0xffffffffu, sq, o);
    }
    if ((tid & 31) == 0) { rs[tid >> 5] = s; rq[tid >> 5] = sq; }
    __syncthreads();
    if (tid < 32) {
        s  = (tid < 8) ? rs[tid] : 0.f;
        sq = (tid < 8) ? rq[tid] : 0.f;
#pragma unroll
        for (int o = 4; o; o >>= 1) {
            s  += __shfl_xor_sync(0xffffffffu, s,  o);
            sq += __shfl_xor_sync(0xffffffffu, sq, o);
        }
        if (tid == 0) { rs[0] = s; rq[0] = sq; }
    }
    __syncthreads();
    const float mean = rs[0] * (1.0f / E_DIM);
    const float var  = rq[0] * (1.0f / E_DIM) - mean * mean;
    const float rstd = rsqrtf(var + 1e-5f);
    __half2* p = (__half2*)&y[(size_t)row * E_DIM + tid * 4];
    p[0] = __halves2half2(__float2half_rn((v.x - mean) * rstd),
                          __float2half_rn((v.y - mean) * rstd));
    p[1] = __halves2half2(__float2half_rn((v.z - mean) * rstd),
                          __float2half_rn((v.w - mean) * rstd));
}

// ======================= fp16 single-pass tensor GEMM =======================
// C[M,N] = A[M,K] * B[N,K]^T
// MODE 1: relu(+bias)->f16 | 2: +res fp32 | 3: +bias+res fp32 | 4: ->f16
#define TILE_BYTES  16384               // 128 rows x 128 bytes (64 fp16)
#define STAGE_BYTES (2 * TILE_BYTES)    // A, B
#define GEMM_STAGES 3
#define GEMM_SMEM   (GEMM_STAGES * STAGE_BYTES)   // 96 KB -> 2 CTAs/SM

template<int MODE>
__global__ __launch_bounds__(256, 2) void gemm_tc(
    const __half* __restrict__ A, const __half* __restrict__ B,
    const float* __restrict__ bias, const float* __restrict__ res,
    float* __restrict__ Cf, __half* __restrict__ Ch,
    int M, int N, int K)
{
    extern __shared__ char smem[];
    const uint32_t sbase = smem_u32(smem);
    const int tid  = threadIdx.x;
    const int wid  = tid >> 5;
    const int lane = tid & 31;
    const int row0 = blockIdx.y * 128;
    const int col0 = blockIdx.x * 128;
    const int wm = (wid & 1) * 64;
    const int wn = (wid >> 1) * 32;

    float acc[4][4][4];
#pragma unroll
    for (int i = 0; i < 4; i++)
#pragma unroll
        for (int j = 0; j < 4; j++)
#pragma unroll
            for (int k = 0; k < 4; k++) acc[i][j][k] = 0.f;

    const int NC = K >> 6;

    auto issue_stage = [&](int c) {
        const uint32_t st = sbase + (c % GEMM_STAGES) * STAGE_BYTES;
        const int k0 = c << 6;
#pragma unroll
        for (int t = 0; t < 2; t++) {
            const __half* g = t ? B : A;
            const int rbase = t ? col0 : row0;
            const uint32_t tb = st + t * TILE_BYTES;
#pragma unroll
            for (int i = 0; i < 4; i++) {
                const int idx = tid + i * 256;
                const int r = idx >> 3, cc = idx & 7;
                cp_async16(tb + r * 128 + ((cc ^ (r & 7)) << 4),
                           g + (size_t)(rbase + r) * K + k0 + cc * 8);
            }
        }
        cp_commit();
    };

    issue_stage(0);
    if (NC > 1) issue_stage(1);

    for (int c = 0; c < NC; c++) {
        if (c < NC - 1) cp_wait<1>();
        else            cp_wait<0>();
        __syncthreads();
        if (c + 2 < NC) issue_stage(c + 2);

        const uint32_t st = sbase + (c % GEMM_STAGES) * STAGE_BYTES;
        const uint32_t sA = st;
        const uint32_t sB = st + TILE_BYTES;
        const int g  = lane >> 3;
        const int lr = lane & 7;

#pragma unroll
        for (int ks = 0; ks < 4; ks++) {
            const int kc0 = ks * 2;
            uint32_t af[4][4], bf[4][2];
#pragma unroll
            for (int mt = 0; mt < 4; mt++) {
                const int row = wm + mt * 16 + lr + (g & 1) * 8;
                const int ch  = kc0 + (g >> 1);
                const uint32_t off = row * 128 + ((ch ^ (row & 7)) << 4);
                ldsm_x4(af[mt], sA + off);
            }
#pragma unroll
            for (int np = 0; np < 2; np++) {
                const int row = wn + np * 16 + lr + (g >> 1) * 8;
                const int ch  = kc0 + (g & 1);
                const uint32_t off = row * 128 + ((ch ^ (row & 7)) << 4);
                uint32_t t0[4];
                ldsm_x4(t0, sB + off);
                bf[np*2][0] = t0[0]; bf[np*2][1] = t0[1];
                bf[np*2+1][0] = t0[2]; bf[np*2+1][1] = t0[3];
            }
#pragma unroll
            for (int mt = 0; mt < 4; mt++)
#pragma unroll
                for (int nt = 0; nt < 4; nt++)
                    mma16816(acc[mt][nt], af[mt], bf[nt][0], bf[nt][1]);
        }
    }

#pragma unroll
    for (int mt = 0; mt < 4; mt++) {
#pragma unroll
        for (int nt = 0; nt < 4; nt++) {
            const int r0 = row0 + wm + mt * 16 + (lane >> 2);
            const int r1 = r0 + 8;
            const int cc = col0 + wn + nt * 8 + (lane & 3) * 2;
            float v0 = acc[mt][nt][0], v1 = acc[mt][nt][1];
            float v2 = acc[mt][nt][2], v3 = acc[mt][nt][3];
            if (MODE == 1 || MODE == 3) {
                const float b0 = bias[cc], b1 = bias[cc + 1];
                v0 += b0; v1 += b1; v2 += b0; v3 += b1;
            }
            if (MODE == 1) {
                v0 = fmaxf(v0, 0.f); v1 = fmaxf(v1, 0.f);
                v2 = fmaxf(v2, 0.f); v3 = fmaxf(v3, 0.f);
            }
            if (MODE == 2 || MODE == 3) {
                float2 ra = *(const float2*)&res[(size_t)r0 * N + cc];
                float2 rb = *(const float2*)&res[(size_t)r1 * N + cc];
                v0 += ra.x; v1 += ra.y; v2 += rb.x; v3 += rb.y;
            }
            if (MODE == 1 || MODE == 4) {
                *(__half2*)&Ch[(size_t)r0 * N + cc] =
                    __halves2half2(__float2half_rn(v0), __float2half_rn(v1));
                *(__half2*)&Ch[(size_t)r1 * N + cc] =
                    __halves2half2(__float2half_rn(v2), __float2half_rn(v3));
            } else {
                *(float2*)&Cf[(size_t)r0 * N + cc] = {v0, v1};
                *(float2*)&Cf[(size_t)r1 * N + cc] = {v2, v3};
            }
        }
    }
}

// ======================= fp16 single-pass MMA causal flash attention =======================
// CTA: 128 q rows (8 warps x 16). KV tiles of 64 rows, double-buffered.
// smem: Q 16K | stage{K 8K, V 8K} x2 = 48 KB. 2 CTAs/SM.
#define ATT_SMEM 49152

__global__ __launch_bounds__(256, 2) void attn_mma(
    const __half* __restrict__ qkv,
    __half* __restrict__ o)
{
    extern __shared__ char smem[];
    const uint32_t sb = smem_u32(smem);
    const int tid = threadIdx.x, wid = tid >> 5, lane = tid & 31;
    const int qb = (int)gridDim.x - 1 - (int)blockIdx.x;   // longest blocks first
    const int q0 = qb * 128;
    const int h  = blockIdx.y, b = blockIdx.z;
    const int LD = 3 * E_DIM;
    const size_t base = (size_t)b * SEQ * LD + (size_t)h * HDIM;

    const uint32_t sQ = sb;

#pragma unroll
    for (int i = 0; i < 4; i++) {
        const int idx = tid + i * 256;
        const int r = idx >> 3, cc = idx & 7;
        const uint32_t soff = r * 128 + ((cc ^ (r & 7)) << 4);
        cp_async16(sQ + soff, qkv + base + (size_t)(q0 + r) * LD + cc * 8);
    }
    auto issue_kv = [&](int t) {
        const uint32_t st = sb + 16384 + (t & 1) * 16384;
        const int k0 = t * 64;
#pragma unroll
        for (int i = 0; i < 2; i++) {
            const int idx = tid + i * 256;
            const int r = idx >> 3, cc = idx & 7;
            const uint32_t soff = r * 128 + ((cc ^ (r & 7)) << 4);
            cp_async16(st +        soff, qkv + base + E_DIM     + (size_t)(k0 + r) * LD + cc * 8);
            cp_async16(st + 8192 + soff, qkv + base + 2 * E_DIM + (size_t)(k0 + r) * LD + cc * 8);
        }
        cp_commit();
    };
    issue_kv(0);

    const int ntiles = (q0 >> 6) + 2;
    const int g = lane >> 2, tig = lane & 3;
    const int lr = lane & 7, gg = lane >> 3;

    float oacc[8][4];
#pragma unroll
    for (int j = 0; j < 8; j++)
#pragma unroll
        for (int e = 0; e < 4; e++) oacc[j][e] = 0.f;
    float m0 = -CUDART_INF_F, m1 = -CUDART_INF_F, l0 = 0.f, l1 = 0.f;
    uint32_t qf[4][4];
    const float scale = 0.125f;

    for (int t = 0; t < ntiles; t++) {
        if (t + 1 < ntiles) { issue_kv(t + 1); cp_wait<1>(); }
        else                { cp_wait<0>(); }
        __syncthreads();
        if (t == 0) {
            const int row = wid * 16 + lr + (gg & 1) * 8;
#pragma unroll
            for (int kc = 0; kc < 4; kc++) {
                const int ch = kc * 2 + (gg >> 1);
                const uint32_t off = row * 128 + ((ch ^ (row & 7)) << 4);
                ldsm_x4(qf[kc], sQ + off);
            }
        }
        const uint32_t sK = sb + 16384 + (t & 1) * 16384;
        const uint32_t sV = sK + 8192;

        // ---- S = Q K^T ----
        float S[8][4];
#pragma unroll
        for (int j = 0; j < 8; j++)
#pragma unroll
            for (int e = 0; e < 4; e++) S[j][e] = 0.f;
#pragma unroll
        for (int kc = 0; kc < 4; kc++) {
            uint32_t bh[8][2];
#pragma unroll
            for (int jp = 0; jp < 4; jp++) {
                const int row = jp * 16 + lr + (gg >> 1) * 8;
                const int ch  = kc * 2 + (gg & 1);
                const uint32_t off = row * 128 + ((ch ^ (row & 7)) << 4);
                uint32_t t0[4];
                ldsm_x4(t0, sK + off);
                bh[jp*2][0] = t0[0]; bh[jp*2][1] = t0[1];
                bh[jp*2+1][0] = t0[2]; bh[jp*2+1][1] = t0[3];
            }
#pragma unroll
            for (int j = 0; j < 8; j++)
                mma16816(S[j], qf[kc], bh[j][0], bh[j][1]);
        }

        // ---- scale + causal mask ----
        const int k0 = t * 64;
        const int r0 = q0 + wid * 16 + g, r1 = r0 + 8;
        const bool need_mask = (k0 + 63 > q0 + wid * 16);
#pragma unroll
        for (int j = 0; j < 8; j++) {
#pragma unroll
            for (int e = 0; e < 4; e++) S[j][e] *= scale;
            if (need_mask) {
                const int c0 = k0 + j * 8 + tig * 2, c1 = c0 + 1;
                if (c0 > r0) S[j][0] = -CUDART_INF_F;
                if (c1 > r0) S[j][1] = -CUDART_INF_F;
                if (c0 > r1) S[j][2] = -CUDART_INF_F;
                if (c1 > r1) S[j][3] = -CUDART_INF_F;
            }
        }

        // ---- online softmax ----
        float rx0 = -CUDART_INF_F, rx1 = -CUDART_INF_F;
#pragma unroll
        for (int j = 0; j < 8; j++) {
            rx0 = fmaxf(rx0, fmaxf(S[j][0], S[j][1]));
            rx1 = fmaxf(rx1, fmaxf(S[j][2], S[j][3]));
        }
        rx0 = fmaxf(rx0, __shfl_xor_sync(0xffffffffu, rx0, 1));
        rx0 = fmaxf(rx0, __shfl_xor_sync(0xffffffffu, rx0, 2));
        rx1 = fmaxf(rx1, __shfl_xor_sync(0xffffffffu, rx1, 1));
        rx1 = fmaxf(rx1, __shfl_xor_sync(0xffffffffu, rx1, 2));
        const float nm0 = fmaxf(m0, rx0), nm1 = fmaxf(m1, rx1);
        const float cr0 = __expf(m0 - nm0), cr1 = __expf(m1 - nm1);
        float sm0 = 0.f, sm1 = 0.f;
#pragma unroll
        for (int j = 0; j < 8; j++) {
            S[j][0] = __expf(S[j][0] - nm0); sm0 += S[j][0];
            S[j][1] = __expf(S[j][1] - nm0); sm0 += S[j][1];
            S[j][2] = __expf(S[j][2] - nm1); sm1 += S[j][2];
            S[j][3] = __expf(S[j][3] - nm1); sm1 += S[j][3];
        }
        sm0 += __shfl_xor_sync(0xffffffffu, sm0, 1);
        sm0 += __shfl_xor_sync(0xffffffffu, sm0, 2);
        sm1 += __shfl_xor_sync(0xffffffffu, sm1, 1);
        sm1 += __shfl_xor_sync(0xffffffffu, sm1, 2);
        l0 = l0 * cr0 + sm0; l1 = l1 * cr1 + sm1;
        m0 = nm0; m1 = nm1;
#pragma unroll
        for (int j = 0; j < 8; j++) {
            oacc[j][0] *= cr0; oacc[j][1] *= cr0;
            oacc[j][2] *= cr1; oacc[j][3] *= cr1;
        }

        // ---- O += P V (single pass) ----
        const int kvr = (lane & 15);
#pragma unroll
        for (int kc = 0; kc < 4; kc++) {
            uint32_t pf[4];
            {
                __half2 p0 = __floats2half2_rn(S[2*kc][0],   S[2*kc][1]);
                __half2 p1 = __floats2half2_rn(S[2*kc][2],   S[2*kc][3]);
                __half2 p2 = __floats2half2_rn(S[2*kc+1][0], S[2*kc+1][1]);
                __half2 p3 = __floats2half2_rn(S[2*kc+1][2], S[2*kc+1][3]);
                pf[0] = *(uint32_t*)&p0; pf[1] = *(uint32_t*)&p1;
                pf[2] = *(uint32_t*)&p2; pf[3] = *(uint32_t*)&p3;
            }
            const int vr = kc * 16 + kvr;
#pragma unroll
            for (int j = 0; j < 8; j++) {
                const uint32_t off = vr * 128 + ((j ^ (vr & 7)) << 4);
                uint32_t vh[2];
                ldsm_x2_trans(vh, sV + off);
                mma16816(oacc[j], pf, vh[0], vh[1]);
            }
        }
        __syncthreads();
    }

    // ---- write O (fp16) ----
    const float i0 = 1.0f / l0, i1 = 1.0f / l1;
    const int row0 = q0 + wid * 16 + g;
    const size_t gr0 = ((size_t)b * SEQ + row0) * E_DIM;
    const size_t gr1 = gr0 + 8 * E_DIM;
#pragma unroll
    for (int j = 0; j < 8; j++) {
        const int c = h * HDIM + j * 8 + tig * 2;
        *(__half2*)&o[gr0 + c] = __floats2half2_rn(oacc[j][0] * i0, oacc[j][1] * i0);
        *(__half2*)&o[gr1 + c] = __floats2half2_rn(oacc[j][2] * i1, oacc[j][3] * i1);
    }
}

// ======================= launch =======================
extern "C" void kernel_launch(void* const* d_in, const int* in_sizes, int n_in,
                              void* d_out, int out_size) {
    const float* x      = (const float*)d_in[0];
    const float* w_in   = (const float*)d_in[1];
    const float* w_out  = (const float*)d_in[2];
    const float* w_fc   = (const float*)d_in[3];
    const float* b_fc   = (const float*)d_in[4];
    const float* w_proj = (const float*)d_in[5];
    const float* b_proj = (const float*)d_in[6];
    float* out = (float*)d_out;

    __half *hb, *ob, *mb, *wi, *wo, *wf, *wp;
    float *x2;
    cudaGetSymbolAddress((void**)&hb, g_h);
    cudaGetSymbolAddress((void**)&ob, g_o);
    cudaGetSymbolAddress((void**)&x2, g_x2);
    cudaGetSymbolAddress((void**)&mb, g_mb);
    cudaGetSymbolAddress((void**)&wi, g_wi); cudaGetSymbolAddress((void**)&wo, g_wo);
    cudaGetSymbolAddress((void**)&wf, g_wf); cudaGetSymbolAddress((void**)&wp, g_wp);

    cudaFuncSetAttribute(gemm_tc<1>, cudaFuncAttributeMaxDynamicSharedMemorySize, GEMM_SMEM);
    cudaFuncSetAttribute(gemm_tc<2>, cudaFuncAttributeMaxDynamicSharedMemorySize, GEMM_SMEM);
    cudaFuncSetAttribute(gemm_tc<3>, cudaFuncAttributeMaxDynamicSharedMemorySize, GEMM_SMEM);
    cudaFuncSetAttribute(gemm_tc<4>, cudaFuncAttributeMaxDynamicSharedMemorySize, GEMM_SMEM);
    cudaFuncSetAttribute(attn_mma,   cudaFuncAttributeMaxDynamicSharedMemorySize, ATT_SMEM);

    cvt_all<<<2048, 256>>>(w_in, w_out, w_fc, w_proj, wi, wo, wf, wp);

    // h = ln(x) -> fp16
    ln_kernel<<<MTOT, 256>>>(x, hb);
    // qkv = h @ w_in^T -> fp16 (into mb)
    gemm_tc<4><<<dim3(3 * E_DIM / 128, MTOT / 128), 256, GEMM_SMEM>>>(
        hb, wi, nullptr, nullptr, nullptr, mb, MTOT, 3 * E_DIM, E_DIM);
    // o = causal_attn(qkv) -> fp16
    attn_mma<<<dim3(SEQ / 128, NHEAD, BATCH), 256, ATT_SMEM>>>(mb, ob);
    // x2 = x + o @ w_out^T
    gemm_tc<2><<<dim3(E_DIM / 128, MTOT / 128), 256, GEMM_SMEM>>>(
        ob, wo, nullptr, x, x2, nullptr, MTOT, E_DIM, E_DIM);
    // h = ln(x2) -> fp16
    ln_kernel<<<MTOT, 256>>>(x2, hb);
    // mb = relu(h @ w_fc^T + b_fc) -> fp16
    gemm_tc<1><<<dim3(4 * E_DIM / 128, MTOT / 128), 256, GEMM_SMEM>>>(
        hb, wf, b_fc, nullptr, nullptr, mb, MTOT, 4 * E_DIM, E_DIM);
    // out = mb @ w_proj^T + b_proj + x2
    gemm_tc<3><<<dim3(E_DIM / 128, MTOT / 128), 256, GEMM_SMEM>>>(
        mb, wp, b_proj, x2, out, nullptr, MTOT, E_DIM, 4 * E_DIM);
}